// round 15
// baseline (speedup 1.0000x reference)
#include <cuda_runtime.h>
#include <cuda_bf16.h>
#include <cstdint>
#include <stdint.h>
#include <math.h>

#define NN 100000
#define EE 500000
#define RR 3
#define LL 2
#define FF 300
#define HH 256
#define CC 23
#define NH (NN*HH)
#define KCAT (RR*HH)          // 768
#define KCATP 1024            // [m0|m1|m2|h] concat width
#define XKP 320               // FF padded to 32-multiple

// Bt plane element offsets
#define BT_FEAT 0
#define BT_L0   (BT_FEAT + HH*XKP)      // combined [gcn/3 | skip], width 1024
#define BT_L1   (BT_L0 + HH*KCATP)
#define BT_C1   (BT_L1 + HH*KCATP)
#define BT_C2   (BT_C1 + HH*HH)         // head W_c2 padded to [32][256]
#define BT_TOT  (BT_C2 + 32*HH)

// ---------------- scratch (device globals; no cudaMalloc allowed) ----------------
__device__ float d_h[NH];
__device__ float d_t[NH];
__device__ float d_rs[RR*NN];
__device__ float d_rd[RR*NN];
__device__ int   d_cnts[RR*NN];
__device__ int   d_cntd[RR*NN];
__device__ int   d_off[RR*(NN+1)];
__device__ int   d_cur[RR*NN];
__device__ int   d_adj[RR*EE];
__device__ float d_stats[2*HH];
__device__ float d_ab[2*HH];
__device__ float d_biasL[LL*HH];
__device__ int   d_part[RR*256];
// bf16 hi/lo planes (uint4 = 8 bf16)
__device__ uint4 d_xhi[(size_t)NN*XKP/8],   d_xlo[(size_t)NN*XKP/8];
__device__ uint4 d_chi[(size_t)NN*KCATP/8], d_clo[(size_t)NN*KCATP/8];
__device__ uint4 d_bthi[BT_TOT/8],          d_btlo[BT_TOT/8];

// ---------------- PTX helpers (base sm_103 compatible only) ----------------
__device__ __forceinline__ uint32_t smem_u32(const void* p) {
    uint32_t a;
    asm("{ .reg .u64 t; cvta.to.shared.u64 t, %1; cvt.u32.u64 %0, t; }" : "=r"(a) : "l"(p));
    return a;
}
__device__ __forceinline__ void cpa16(uint32_t dst, const void* src) {
    asm volatile("cp.async.cg.shared.global [%0], [%1], 16;" :: "r"(dst), "l"(src));
}
__device__ __forceinline__ void ldsm4(uint32_t* r, uint32_t addr) {
    asm volatile("ldmatrix.sync.aligned.m8n8.x4.shared.b16 {%0,%1,%2,%3}, [%4];"
        : "=r"(r[0]), "=r"(r[1]), "=r"(r[2]), "=r"(r[3]) : "r"(addr));
}
__device__ __forceinline__ void mma16816(float* c, const uint32_t* a, const uint32_t* b) {
    asm volatile("mma.sync.aligned.m16n8k16.row.col.f32.bf16.bf16.f32 "
        "{%0,%1,%2,%3}, {%4,%5,%6,%7}, {%8,%9}, {%0,%1,%2,%3};"
        : "+f"(c[0]), "+f"(c[1]), "+f"(c[2]), "+f"(c[3])
        : "r"(a[0]), "r"(a[1]), "r"(a[2]), "r"(a[3]), "r"(b[0]), "r"(b[1]));
}
__device__ __forceinline__ void split2(float a, float b, uint32_t& hi, uint32_t& lo) {
    __nv_bfloat16 ha = __float2bfloat16(a), hb = __float2bfloat16(b);
    __nv_bfloat16 la = __float2bfloat16(a - __bfloat162float(ha));
    __nv_bfloat16 lb = __float2bfloat16(b - __bfloat162float(hb));
    hi = ((uint32_t)__bfloat16_as_ushort(hb) << 16) | __bfloat16_as_ushort(ha);
    lo = ((uint32_t)__bfloat16_as_ushort(lb) << 16) | __bfloat16_as_ushort(la);
}

// ---------------- graph build ----------------
__global__ void zero_graph_k() {
    int i = blockIdx.x*blockDim.x + threadIdx.x;
    if (i < RR*NN) { d_cnts[i]=0; d_cntd[i]=0; d_cur[i]=0; }
}
__global__ void count_k(const int* __restrict__ src, const int* __restrict__ dst) {
    int idx = blockIdx.x*blockDim.x + threadIdx.x;
    if (idx < RR*EE) {
        int r = idx / EE;
        atomicAdd(&d_cnts[r*NN + src[idx]], 1);
        atomicAdd(&d_cntd[r*NN + dst[idx]], 1);
    }
}
__global__ void degs_k() {
    int i = blockIdx.x*blockDim.x + threadIdx.x;
    if (i < RR*NN) {
        int cs = d_cnts[i]; if (cs < 1) cs = 1;
        int cd = d_cntd[i]; if (cd < 1) cd = 1;
        d_rs[i] = rsqrtf((float)cs);
        d_rd[i] = rsqrtf((float)cd);
    }
}
// merged over relations via blockIdx.y
__global__ void scan_part_k() {
    __shared__ int sh[512];
    int r = blockIdx.y;
    const int* cnt = d_cntd + r*NN;
    int i = threadIdx.x;
    int d = blockIdx.x*512 + i;
    sh[i] = (d < NN) ? cnt[d] : 0;
    __syncthreads();
    for (int s = 256; s > 0; s >>= 1) { if (i < s) sh[i] += sh[i+s]; __syncthreads(); }
    if (i == 0) d_part[r*256 + blockIdx.x] = sh[0];
}
__global__ void scan_top_k(int nblk) {
    int r = threadIdx.x;
    if (r < RR) {
        int* part = d_part + r*256;
        int run = 0;
        for (int i = 0; i < nblk; i++) { int v = part[i]; part[i] = run; run += v; }
        d_off[r*(NN+1) + NN] = run;
    }
}
__global__ void scan_fill_k() {
    __shared__ int sh[512];
    int r = blockIdx.y;
    const int* cnt = d_cntd + r*NN;
    int i = threadIdx.x;
    int d = blockIdx.x*512 + i;
    int v = (d < NN) ? cnt[d] : 0;
    sh[i] = v;
    __syncthreads();
    for (int s = 1; s < 512; s <<= 1) {
        int tv = (i >= s) ? sh[i-s] : 0;
        __syncthreads();
        sh[i] += tv;
        __syncthreads();
    }
    if (d < NN) d_off[r*(NN+1) + d] = d_part[r*256 + blockIdx.x] + sh[i] - v;
}
__global__ void fill_adj_k(const int* __restrict__ src, const int* __restrict__ dst) {
    int idx = blockIdx.x*blockDim.x + threadIdx.x;
    if (idx < RR*EE) {
        int r = idx / EE;
        int dd = dst[idx];
        int p = d_off[r*(NN+1) + dd] + atomicAdd(&d_cur[r*NN + dd], 1);
        d_adj[r*EE + p] = src[idx];
    }
}

// ---------------- aggregation: bf16 hi/lo planes into cat cols [r*256, r*256+256) ----------------
__global__ void spmm_all_k(const float4* __restrict__ h4) {
    int d = blockIdx.x;
    int r = blockIdx.y;
    int j = threadIdx.x;               // 64 threads -> 64 float4 columns
    const int* off = d_off + r*(NN+1);
    const int* adj = d_adj + r*EE;
    const float* rs = d_rs + r*NN;
    int beg = off[d], end = off[d+1];
    float ax=0.f, ay=0.f, az=0.f, aw=0.f;
    int e = beg;
    for (; e + 1 < end; e += 2) {
        int s0 = adj[e], s1 = adj[e+1];
        float w0 = rs[s0], w1 = rs[s1];
        float4 v0 = h4[(size_t)s0*(HH/4) + j];
        float4 v1 = h4[(size_t)s1*(HH/4) + j];
        ax += v0.x*w0 + v1.x*w1;
        ay += v0.y*w0 + v1.y*w1;
        az += v0.z*w0 + v1.z*w1;
        aw += v0.w*w0 + v1.w*w1;
    }
    if (e < end) {
        int s0 = adj[e];
        float w0 = rs[s0];
        float4 v0 = h4[(size_t)s0*(HH/4) + j];
        ax += v0.x*w0; ay += v0.y*w0; az += v0.z*w0; aw += v0.w*w0;
    }
    float wd = d_rd[r*NN + d];
    ax *= wd; ay *= wd; az *= wd; aw *= wd;
    uint32_t h01, l01, h23, l23;
    split2(ax, ay, h01, l01);
    split2(az, aw, h23, l23);
    size_t u2 = (size_t)d*(KCATP/4) + r*(HH/4) + j;
    ((uint2*)d_chi)[u2] = make_uint2(h01, h23);
    ((uint2*)d_clo)[u2] = make_uint2(l01, l23);
}

// ---------------- weight pack: W seg [Kseg rows][256] fp32 -> B^T planes [256][Kp] at col kofs ----------------
__global__ void pack_seg_k(const float* __restrict__ W, int Ksrc, int Kseg,
                           int Kp, int kofs, int base, float scale) {
    int idx = blockIdx.x*blockDim.x + threadIdx.x;
    if (idx >= HH*Kseg) return;
    int n = idx / Kseg, k = idx % Kseg;
    float v = (k < Ksrc) ? W[(size_t)k*HH + n] * scale : 0.f;
    __nv_bfloat16 hi = __float2bfloat16(v);
    __nv_bfloat16 lo = __float2bfloat16(v - __bfloat162float(hi));
    size_t o = (size_t)base + (size_t)n*Kp + kofs + k;
    ((__nv_bfloat16*)d_bthi)[o] = hi;
    ((__nv_bfloat16*)d_btlo)[o] = lo;
}

// head pack: W_c2 [256][23] -> Bt planes [32][256] (rows >= 23 zero)
__global__ void pack_head_k(const float* __restrict__ W) {
    int idx = blockIdx.x*blockDim.x + threadIdx.x;
    if (idx >= 32*HH) return;
    int n = idx / HH, k = idx % HH;
    float v = (n < CC) ? W[(size_t)k*CC + n] : 0.f;
    __nv_bfloat16 hi = __float2bfloat16(v);
    __nv_bfloat16 lo = __float2bfloat16(v - __bfloat162float(hi));
    ((__nv_bfloat16*)d_bthi)[BT_C2 + idx] = hi;
    ((__nv_bfloat16*)d_btlo)[BT_C2 + idx] = lo;
}

// combined layer bias: mean(gcn_b) + skip_b
__global__ void comb_bias_k(const float* __restrict__ gcn_b, const float* __restrict__ skip_b) {
    int i = threadIdx.x + blockIdx.x*blockDim.x;
    if (i < LL*HH) {
        int l = i / HH, c = i % HH;
        const float* gb = gcn_b + (size_t)l*RR*HH;
        d_biasL[i] = (gb[c] + gb[HH+c] + gb[2*HH+c]) * (1.f/3.f) + skip_b[(size_t)l*HH + c];
    }
}

// ---------------- x convert: [N][300] fp32 -> planes [N][320] ----------------
__global__ void conv_x_k(const float* __restrict__ x) {
    int idx = blockIdx.x*blockDim.x + threadIdx.x;
    if (idx >= NN*XKP) return;
    int r = idx / XKP, k = idx % XKP;
    float v = (k < FF) ? x[(size_t)r*FF + k] : 0.f;
    __nv_bfloat16 hi = __float2bfloat16(v);
    __nv_bfloat16 lo = __float2bfloat16(v - __bfloat162float(hi));
    ((__nv_bfloat16*)d_xhi)[idx] = hi;
    ((__nv_bfloat16*)d_xlo)[idx] = lo;
}

// ---------------- tensor-core GEMM: C[M,256] = A[M,K] @ B^T (+bias) + fused BN stats ----------------
// CTA tile 64x256, 8 warps (2M x 4N), warp tile 32x64, k-chunk 32, 2-stage cp.async.
// Stage (40960B): A_hi[0,4K) A_lo[4K,8K) B_hi[8K,24K) B_lo[24K,40K)
#define STG 40960
#define GSMEM (2*STG)

__device__ __forceinline__ void g_load_stage(char* smemc, uint32_t sb, int st, int tid,
        int m0, int kc, int lda, int Kp,
        const __nv_bfloat16* Ahi, const __nv_bfloat16* Alo,
        const __nv_bfloat16* Bhi, const __nv_bfloat16* Blo)
{
    uint32_t base = sb + st*STG;
    char* cbase = smemc + st*STG;
    {
        int c = tid;                   // 256 A-chunks of 16B per plane
        int row = c >> 2, kp = c & 3;
        int gr = m0 + row;
        uint32_t off = row*64 + ((kp*16) ^ (((row>>1)&3)<<4));
        if (gr < NN) {
            size_t g = (size_t)gr*lda + kc*32 + kp*8;
            cpa16(base + off, Ahi + g);
            cpa16(base + 4096 + off, Alo + g);
        } else {
            *(uint4*)(cbase + off) = make_uint4(0,0,0,0);
            *(uint4*)(cbase + 4096 + off) = make_uint4(0,0,0,0);
        }
    }
    #pragma unroll
    for (int i = 0; i < 4; i++) {      // 1024 B-chunks per plane
        int c = tid + i*256;
        int n = c >> 2, kp = c & 3;
        uint32_t off = 8192 + n*64 + ((kp*16) ^ (((n>>1)&3)<<4));
        size_t g = (size_t)n*Kp + kc*32 + kp*8;
        cpa16(base + off, Bhi + g);
        cpa16(base + 16384 + off, Blo + g);
    }
    asm volatile("cp.async.commit_group;" ::: "memory");
}

__device__ __forceinline__ void g_compute_stage(uint32_t sb, int st, int lane, int wm, int wn,
        float acc[2][8][4])
{
    uint32_t aS = sb + st*STG;
    uint32_t bS = aS + 8192;
    #pragma unroll
    for (int k16 = 0; k16 < 2; k16++) {
        uint32_t ah[2][4], al[2][4];
        int arow = lane & 15;
        int akb = k16*32 + ((lane >> 4) << 4);
        #pragma unroll
        for (int t = 0; t < 2; t++) {
            int r = wm*32 + t*16 + arow;
            uint32_t ad = aS + r*64 + (akb ^ (((r>>1)&3)<<4));
            ldsm4(ah[t], ad);
            ldsm4(al[t], ad + 4096);
        }
        // B via ldmatrix.x4: matrices 0,1 = n-tile u2*2 (k0-7, k8-15);
        // matrices 2,3 = n-tile u2*2+1 (lanes 16-31 supply base_n + 8)
        uint32_t bh[8][2], bl[8][2];
        int bn_ = lane & 7;
        int nofs = ((lane >> 4) & 1) * 8;
        int bkb = k16*32 + (((lane>>3)&1) << 4);
        #pragma unroll
        for (int u2 = 0; u2 < 4; u2++) {
            int n = wn*64 + u2*16 + nofs + bn_;
            uint32_t bd = bS + n*64 + (bkb ^ (((n>>1)&3)<<4));
            ldsm4(&bh[u2*2][0], bd);
            ldsm4(&bl[u2*2][0], bd + 16384);
        }
        #pragma unroll
        for (int t = 0; t < 2; t++)
            #pragma unroll
            for (int u = 0; u < 8; u++) {
                mma16816(acc[t][u], ah[t], bh[u]);
                mma16816(acc[t][u], ah[t], bl[u]);
                mma16816(acc[t][u], al[t], bh[u]);
            }
    }
}

__global__ void __launch_bounds__(256) gemm_mma_k(
        const __nv_bfloat16* __restrict__ Ahi, const __nv_bfloat16* __restrict__ Alo,
        int lda, int Kp,
        const __nv_bfloat16* __restrict__ Bhi, const __nv_bfloat16* __restrict__ Blo,
        const float* __restrict__ bias, float* __restrict__ C)
{
    extern __shared__ char smemc[];
    uint32_t sb = smem_u32(smemc);
    int tid = threadIdx.x, lane = tid & 31, wid = tid >> 5;
    int m0 = blockIdx.x * 64;
    int wm = wid & 1, wn = wid >> 1;

    float acc[2][8][4];
    #pragma unroll
    for (int t = 0; t < 2; t++)
        #pragma unroll
        for (int u = 0; u < 8; u++)
            #pragma unroll
            for (int q = 0; q < 4; q++) acc[t][u][q] = 0.f;

    int nch = Kp >> 5;
    // verified double-buffer: issue-next FIRST, then wait_group 1, sync, compute, sync
    g_load_stage(smemc, sb, 0, tid, m0, 0, lda, Kp, Ahi, Alo, Bhi, Blo);
    for (int kc = 0; kc < nch; kc++) {
        int st = kc & 1;
        if (kc + 1 < nch) {
            g_load_stage(smemc, sb, st^1, tid, m0, kc+1, lda, Kp, Ahi, Alo, Bhi, Blo);
            asm volatile("cp.async.wait_group 1;" ::: "memory");
        } else {
            asm volatile("cp.async.wait_group 0;" ::: "memory");
        }
        __syncthreads();
        g_compute_stage(sb, st, lane, wm, wn, acc);
        __syncthreads();
    }

    // ---- epilogue: bias + store + fused BN stats (sum, sumsq per column) ----
    float s0[16], s1[16];
    #pragma unroll
    for (int i = 0; i < 16; i++) { s0[i] = 0.f; s1[i] = 0.f; }
    #pragma unroll
    for (int t = 0; t < 2; t++) {
        int r0 = m0 + wm*32 + t*16 + (lane >> 2);
        #pragma unroll
        for (int u = 0; u < 8; u++) {
            int c0 = wn*64 + u*8 + (lane & 3)*2;
            float b0 = bias ? bias[c0]   : 0.f;
            float b1 = bias ? bias[c0+1] : 0.f;
            float v0 = acc[t][u][0] + b0;
            float v1 = acc[t][u][1] + b1;
            float v2 = acc[t][u][2] + b0;
            float v3 = acc[t][u][3] + b1;
            if (r0 < NN) {
                float2 v; v.x = v0; v.y = v1;
                *(float2*)(C + (size_t)r0*HH + c0) = v;
                s0[u*2+0] += v0; s1[u*2+0] += v0*v0;
                s0[u*2+1] += v1; s1[u*2+1] += v1*v1;
            }
            if (r0 + 8 < NN) {
                float2 v; v.x = v2; v.y = v3;
                *(float2*)(C + (size_t)(r0+8)*HH + c0) = v;
                s0[u*2+0] += v2; s1[u*2+0] += v2*v2;
                s0[u*2+1] += v3; s1[u*2+1] += v3*v3;
            }
        }
    }
    #pragma unroll
    for (int m = 4; m < 32; m <<= 1) {
        #pragma unroll
        for (int i = 0; i < 16; i++) {
            s0[i] += __shfl_xor_sync(0xffffffffu, s0[i], m);
            s1[i] += __shfl_xor_sync(0xffffffffu, s1[i], m);
        }
    }
    if (lane < 4) {
        #pragma unroll
        for (int u = 0; u < 8; u++)
            #pragma unroll
            for (int j = 0; j < 2; j++) {
                int c = wn*64 + u*8 + lane*2 + j;
                atomicAdd(&d_stats[c],      s0[u*2+j]);
                atomicAdd(&d_stats[HH + c], s1[u*2+j]);
            }
    }
}

// ---------------- MMA head: out[N,23] = h[N,256] @ W_c2 + b (bf16x3, B resident in smem) ----------------
// CTA: 128 thr (4 warps), tile 64 rows x 32 cols. B planes [32][256] fully in smem.
// smem: B_hi[0,16K) B_lo[16K,32K) ; A stages at 32K: st*(8K): A_hi[4K] A_lo[4K]
__global__ void __launch_bounds__(128) gemm_head_k(
        const __nv_bfloat16* __restrict__ Ahi, const __nv_bfloat16* __restrict__ Alo,
        int lda,
        const __nv_bfloat16* __restrict__ Bhi, const __nv_bfloat16* __restrict__ Blo,
        const float* __restrict__ bias, float* __restrict__ C)
{
    __shared__ char smemc[49152];
    uint32_t sb = smem_u32(smemc);
    int tid = threadIdx.x, lane = tid & 31, wid = tid >> 5;
    int m0 = blockIdx.x * 64;

    // load full B (8 chunks x 32n x 64B per plane), group 0
    for (int i = tid; i < 1024; i += 128) {
        int c = i >> 7, rem = i & 127;
        int n = rem >> 2, kp = rem & 3;
        uint32_t off = c*2048 + n*64 + ((kp*16) ^ (((n>>1)&3)<<4));
        size_t g = (size_t)n*HH + c*32 + kp*8;
        cpa16(sb + off, Bhi + g);
        cpa16(sb + 16384 + off, Blo + g);
    }
    asm volatile("cp.async.commit_group;" ::: "memory");

    // A stage loader: 64 rows x 32k per plane -> 256 chunks of 16B, 128 thr x2
    auto loadA = [&](int st, int kc) {
        uint32_t base = sb + 32768 + st*8192;
        #pragma unroll
        for (int i = 0; i < 2; i++) {
            int c = tid + i*128;
            int row = c >> 2, kp = c & 3;
            int gr = m0 + row;
            uint32_t off = row*64 + ((kp*16) ^ (((row>>1)&3)<<4));
            if (gr < NN) {
                size_t g = (size_t)gr*lda + kc*32 + kp*8;
                cpa16(base + off, Ahi + g);
                cpa16(base + 4096 + off, Alo + g);
            } else {
                *(uint4*)(smemc + 32768 + st*8192 + off) = make_uint4(0,0,0,0);
                *(uint4*)(smemc + 32768 + st*8192 + 4096 + off) = make_uint4(0,0,0,0);
            }
        }
        asm volatile("cp.async.commit_group;" ::: "memory");
    };

    float acc[4][4];
    #pragma unroll
    for (int u = 0; u < 4; u++)
        #pragma unroll
        for (int q = 0; q < 4; q++) acc[u][q] = 0.f;

    loadA(0, 0);
    for (int kc = 0; kc < 8; kc++) {
        int st = kc & 1;
        if (kc + 1 < 8) {
            loadA(st^1, kc+1);
            asm volatile("cp.async.wait_group 1;" ::: "memory");
        } else {
            asm volatile("cp.async.wait_group 0;" ::: "memory");
        }
        __syncthreads();
        uint32_t aS = sb + 32768 + st*8192;
        uint32_t bS = sb + kc*2048;
        #pragma unroll
        for (int k16 = 0; k16 < 2; k16++) {
            uint32_t ah[4], al[4];
            int r = wid*16 + (lane & 15);
            int akb = k16*32 + ((lane >> 4) << 4);
            uint32_t ad = aS + r*64 + (akb ^ (((r>>1)&3)<<4));
            ldsm4(ah, ad);
            ldsm4(al, ad + 4096);
            uint32_t bh[4][2], bl[4][2];
            int bn_ = lane & 7;
            int nofs = ((lane >> 4) & 1) * 8;
            int bkb = k16*32 + (((lane>>3)&1) << 4);
            #pragma unroll
            for (int u2 = 0; u2 < 2; u2++) {
                int n = u2*16 + nofs + bn_;
                uint32_t bd = bS + n*64 + (bkb ^ (((n>>1)&3)<<4));
                ldsm4(&bh[u2*2][0], bd);
                ldsm4(&bl[u2*2][0], bd + 16384);
            }
            #pragma unroll
            for (int u = 0; u < 4; u++) {
                mma16816(acc[u], ah, bh[u]);
                mma16816(acc[u], ah, bl[u]);
                mma16816(acc[u], al, bh[u]);
            }
        }
        __syncthreads();
    }

    int r0 = m0 + wid*16 + (lane >> 2);
    #pragma unroll
    for (int u = 0; u < 4; u++) {
        int c0 = u*8 + (lane & 3)*2;
        float b0 = (c0 < CC)   ? bias[c0]   : 0.f;
        float b1 = (c0+1 < CC) ? bias[c0+1] : 0.f;
        if (r0 < NN) {
            if (c0 < CC)   C[(size_t)r0*CC + c0]   = acc[u][0] + b0;
            if (c0+1 < CC) C[(size_t)r0*CC + c0+1] = acc[u][1] + b1;
        }
        if (r0 + 8 < NN) {
            if (c0 < CC)   C[(size_t)(r0+8)*CC + c0]   = acc[u][2] + b0;
            if (c0+1 < CC) C[(size_t)(r0+8)*CC + c0+1] = acc[u][3] + b1;
        }
    }
}

// ---------------- BatchNorm ----------------
__global__ void zero_stats_k() {
    int i = threadIdx.x;
    if (i < 2*HH) d_stats[i] = 0.f;
}
// finalize + re-zero stats for the next GEMM's atomics
__global__ void bn_fin_k(const float* __restrict__ g, const float* __restrict__ b) {
    int j = threadIdx.x;
    float mean = d_stats[j] * (1.f/NN);
    float var  = d_stats[HH+j] * (1.f/NN) - mean*mean;
    float a = g[j] * rsqrtf(var + 1e-5f);
    d_ab[j] = a;
    d_ab[HH+j] = b[j] - mean*a;
    d_stats[j] = 0.f;
    d_stats[HH+j] = 0.f;
}
// mode 0: relu, 1: leaky_relu(0.01); planes: also write bf16 hi/lo into cat cols 768..1023
__global__ void bn_apply_k(const float4* __restrict__ in, float4* __restrict__ outp,
                           int mode, int planes) {
    int i = blockIdx.x*blockDim.x + threadIdx.x;
    if (i < NH/4) {
        int j = (i*4) & (HH-1);
        float4 v = in[i];
        float r0 = d_ab[j+0]*v.x + d_ab[HH+j+0];
        float r1 = d_ab[j+1]*v.y + d_ab[HH+j+1];
        float r2 = d_ab[j+2]*v.z + d_ab[HH+j+2];
        float r3 = d_ab[j+3]*v.w + d_ab[HH+j+3];
        if (mode == 0) {
            r0 = fmaxf(r0, 0.f); r1 = fmaxf(r1, 0.f);
            r2 = fmaxf(r2, 0.f); r3 = fmaxf(r3, 0.f);
        } else {
            r0 = (r0 > 0.f) ? r0 : 0.01f*r0;
            r1 = (r1 > 0.f) ? r1 : 0.01f*r1;
            r2 = (r2 > 0.f) ? r2 : 0.01f*r2;
            r3 = (r3 > 0.f) ? r3 : 0.01f*r3;
        }
        float4 o; o.x = r0; o.y = r1; o.z = r2; o.w = r3;
        outp[i] = o;
        if (planes) {
            uint32_t h01, l01, h23, l23;
            split2(r0, r1, h01, l01);
            split2(r2, r3, h23, l23);
            int row = i >> 6;          // HH/4 = 64 float4 per row
            int cj  = i & 63;
            size_t u2 = (size_t)row*(KCATP/4) + (KCAT/4) + cj;
            ((uint2*)d_chi)[u2] = make_uint2(h01, h23);
            ((uint2*)d_clo)[u2] = make_uint2(l01, l23);
        }
    }
}

extern "C" void kernel_launch(void* const* d_in, const int* in_sizes, int n_in,
                              void* d_out, int out_size) {
    (void)in_sizes; (void)n_in; (void)out_size;
    const float* x         = (const float*)d_in[0];
    const int*   esrc      = (const int*)  d_in[1];
    const int*   edst      = (const int*)  d_in[2];
    const float* W_feat    = (const float*)d_in[3];
    const float* b_feat    = (const float*)d_in[4];
    const float* g_feat    = (const float*)d_in[5];
    const float* beta_feat = (const float*)d_in[6];
    const float* gcn_W     = (const float*)d_in[7];
    const float* gcn_b     = (const float*)d_in[8];
    const float* skip_W    = (const float*)d_in[9];
    const float* skip_b    = (const float*)d_in[10];
    const float* bn_g      = (const float*)d_in[11];
    const float* bn_b      = (const float*)d_in[12];
    const float* W_c1      = (const float*)d_in[13];
    const float* b_c1      = (const float*)d_in[14];
    const float* g_c       = (const float*)d_in[15];
    const float* beta_c    = (const float*)d_in[16];
    const float* W_c2      = (const float*)d_in[17];
    const float* b_c2      = (const float*)d_in[18];
    float* out = (float*)d_out;

    float *h, *t, *biasL;
    void *xhi, *xlo, *chi, *clo, *bthi, *btlo;
    cudaGetSymbolAddress((void**)&h,     d_h);
    cudaGetSymbolAddress((void**)&t,     d_t);
    cudaGetSymbolAddress((void**)&biasL, d_biasL);
    cudaGetSymbolAddress(&xhi, d_xhi);   cudaGetSymbolAddress(&xlo, d_xlo);
    cudaGetSymbolAddress(&chi, d_chi);   cudaGetSymbolAddress(&clo, d_clo);
    cudaGetSymbolAddress(&bthi, d_bthi); cudaGetSymbolAddress(&btlo, d_btlo);
    const __nv_bfloat16* XHI = (const __nv_bfloat16*)xhi;
    const __nv_bfloat16* XLO = (const __nv_bfloat16*)xlo;
    const __nv_bfloat16* CHI = (const __nv_bfloat16*)chi;
    const __nv_bfloat16* CLO = (const __nv_bfloat16*)clo;
    const __nv_bfloat16* BHI = (const __nv_bfloat16*)bthi;
    const __nv_bfloat16* BLO = (const __nv_bfloat16*)btlo;

    cudaFuncSetAttribute(gemm_mma_k, cudaFuncAttributeMaxDynamicSharedMemorySize, GSMEM);

    const int NBLK = (NN + 511) / 512;
    const int GG = (NN + 63)/64;

    // ---- launches 1..3, then gemm as my 4th launch (ncu: harness offset 2, -s 5 -> my #4) ----
    conv_x_k<<<(NN*XKP + 255)/256, 256>>>(x);                                   // 1
    pack_seg_k<<<(HH*XKP + 255)/256, 256>>>(W_feat, FF, XKP, XKP, 0, BT_FEAT, 1.f);  // 2
    zero_stats_k<<<1, 512>>>();                                                 // 3
    gemm_mma_k<<<GG, 256, GSMEM>>>(XHI, XLO, XKP, XKP, BHI + BT_FEAT, BLO + BT_FEAT,
                                   b_feat, t);                                  // 4  <- profiled
    bn_fin_k<<<1, 256>>>(g_feat, beta_feat);
    bn_apply_k<<<(NH/4 + 255)/256, 256>>>((const float4*)t, (float4*)h, 0, 1);

    // ---- remaining weight packs + combined biases ----
    pack_seg_k<<<(HH*KCAT + 255)/256, 256>>>(gcn_W,             KCAT, KCAT, KCATP, 0, BT_L0, 1.f/3.f);
    pack_seg_k<<<(HH*HH   + 255)/256, 256>>>(skip_W,            HH, HH, KCATP, KCAT, BT_L0, 1.f);
    pack_seg_k<<<(HH*KCAT + 255)/256, 256>>>(gcn_W + RR*HH*HH,  KCAT, KCAT, KCATP, 0, BT_L1, 1.f/3.f);
    pack_seg_k<<<(HH*HH   + 255)/256, 256>>>(skip_W + HH*HH,    HH, HH, KCATP, KCAT, BT_L1, 1.f);
    pack_seg_k<<<(HH*HH   + 255)/256, 256>>>(W_c1,              HH, HH, HH, 0, BT_C1, 1.f);
    pack_head_k<<<(32*HH + 255)/256, 256>>>(W_c2);
    comb_bias_k<<<2, 256>>>(gcn_b, skip_b);

    // ---- graph build (relations merged via grid.y) ----
    zero_graph_k<<<(RR*NN + 255)/256, 256>>>();
    count_k<<<(RR*EE + 255)/256, 256>>>(esrc, edst);
    degs_k<<<(RR*NN + 255)/256, 256>>>();
    dim3 sp(NBLK, RR);
    scan_part_k<<<sp, 512>>>();
    scan_top_k<<<1, 32>>>(NBLK);
    scan_fill_k<<<sp, 512>>>();
    fill_adj_k<<<(RR*EE + 255)/256, 256>>>(esrc, edst);

    // ---- GCN layers: single fused GEMM per layer (A=[m0|m1|m2|h], K=1024) ----
    for (int l = 0; l < LL; l++) {
        int btl = l ? BT_L1 : BT_L0;
        dim3 sg(NN, RR);
        spmm_all_k<<<sg, 64>>>((const float4*)h);
        gemm_mma_k<<<GG, 256, GSMEM>>>(CHI, CLO, KCATP, KCATP, BHI + btl, BLO + btl,
                                       biasL + l*HH, t);
        bn_fin_k<<<1, 256>>>(bn_g + l*HH, bn_b + l*HH);
        bn_apply_k<<<(NH/4 + 255)/256, 256>>>((const float4*)t, (float4*)h, 1, 1);
    }

    // ---- classification head (A = h planes inside cat buffer, lda=1024) ----
    gemm_mma_k<<<GG, 256, GSMEM>>>(CHI + KCAT, CLO + KCAT, KCATP, HH,
                                   BHI + BT_C1, BLO + BT_C1, b_c1, t);
    bn_fin_k<<<1, 256>>>(g_c, beta_c);
    bn_apply_k<<<(NH/4 + 255)/256, 256>>>((const float4*)t, (float4*)h, 0, 1);
    gemm_head_k<<<GG, 128>>>(CHI + KCAT, CLO + KCAT, KCATP,
                             BHI + BT_C2, BLO + BT_C2, b_c2, out);
}

// round 17
// speedup vs baseline: 1.1171x; 1.1171x over previous
#include <cuda_runtime.h>
#include <cuda_bf16.h>
#include <cstdint>
#include <stdint.h>
#include <math.h>

#define NN 100000
#define EE 500000
#define RR 3
#define LL 2
#define FF 300
#define HH 256
#define CC 23
#define NH (NN*HH)
#define KCAT (RR*HH)          // 768
#define KCATP 1024            // [m0|m1|m2|h] concat width
#define XKP 320               // FF padded to 32-multiple

// Bt plane element offsets
#define BT_FEAT 0
#define BT_L0   (BT_FEAT + HH*XKP)      // combined [gcn/3 | skip], width 1024
#define BT_L1   (BT_L0 + HH*KCATP)
#define BT_C1   (BT_L1 + HH*KCATP)
#define BT_C2   (BT_C1 + HH*HH)         // head W_c2 padded to [32][256]
#define BT_TOT  (BT_C2 + 32*HH)

// ---------------- scratch (device globals; no cudaMalloc allowed) ----------------
__device__ float d_h[NH];
__device__ float d_t[NH];
__device__ float d_rs[RR*NN];
__device__ float d_rd[RR*NN];
__device__ int   d_cnts[RR*NN];
__device__ int   d_cntd[RR*NN];
__device__ int   d_off[RR*(NN+1)];
__device__ int   d_cur[RR*NN];
__device__ int   d_adj[RR*EE];
__device__ float d_stats[2*HH];
__device__ float d_ab[2*HH];
__device__ float d_biasL[LL*HH];
__device__ int   d_part[RR*256];
// bf16 hi/lo planes (uint4 = 8 bf16)
__device__ uint4 d_xhi[(size_t)NN*XKP/8],   d_xlo[(size_t)NN*XKP/8];
__device__ uint4 d_chi[(size_t)NN*KCATP/8], d_clo[(size_t)NN*KCATP/8];
__device__ uint4 d_bthi[BT_TOT/8],          d_btlo[BT_TOT/8];

// ---------------- PTX helpers (base sm_103 compatible only) ----------------
__device__ __forceinline__ uint32_t smem_u32(const void* p) {
    uint32_t a;
    asm("{ .reg .u64 t; cvta.to.shared.u64 t, %1; cvt.u32.u64 %0, t; }" : "=r"(a) : "l"(p));
    return a;
}
__device__ __forceinline__ void cpa16(uint32_t dst, const void* src) {
    asm volatile("cp.async.cg.shared.global [%0], [%1], 16;" :: "r"(dst), "l"(src));
}
__device__ __forceinline__ void ldsm4(uint32_t* r, uint32_t addr) {
    asm volatile("ldmatrix.sync.aligned.m8n8.x4.shared.b16 {%0,%1,%2,%3}, [%4];"
        : "=r"(r[0]), "=r"(r[1]), "=r"(r[2]), "=r"(r[3]) : "r"(addr));
}
__device__ __forceinline__ void ldsm2(uint32_t* r, uint32_t addr) {
    asm volatile("ldmatrix.sync.aligned.m8n8.x2.shared.b16 {%0,%1}, [%2];"
        : "=r"(r[0]), "=r"(r[1]) : "r"(addr));
}
__device__ __forceinline__ void mma16816(float* c, const uint32_t* a, const uint32_t* b) {
    asm volatile("mma.sync.aligned.m16n8k16.row.col.f32.bf16.bf16.f32 "
        "{%0,%1,%2,%3}, {%4,%5,%6,%7}, {%8,%9}, {%0,%1,%2,%3};"
        : "+f"(c[0]), "+f"(c[1]), "+f"(c[2]), "+f"(c[3])
        : "r"(a[0]), "r"(a[1]), "r"(a[2]), "r"(a[3]), "r"(b[0]), "r"(b[1]));
}
__device__ __forceinline__ void split2(float a, float b, uint32_t& hi, uint32_t& lo) {
    __nv_bfloat16 ha = __float2bfloat16(a), hb = __float2bfloat16(b);
    __nv_bfloat16 la = __float2bfloat16(a - __bfloat162float(ha));
    __nv_bfloat16 lb = __float2bfloat16(b - __bfloat162float(hb));
    hi = ((uint32_t)__bfloat16_as_ushort(hb) << 16) | __bfloat16_as_ushort(ha);
    lo = ((uint32_t)__bfloat16_as_ushort(lb) << 16) | __bfloat16_as_ushort(la);
}

// ---------------- graph build ----------------
__global__ void zero_graph_k() {
    int i = blockIdx.x*blockDim.x + threadIdx.x;
    if (i < RR*NN) { d_cnts[i]=0; d_cntd[i]=0; d_cur[i]=0; }
}
__global__ void count_k(const int* __restrict__ src, const int* __restrict__ dst) {
    int idx = blockIdx.x*blockDim.x + threadIdx.x;
    if (idx < RR*EE) {
        int r = idx / EE;
        atomicAdd(&d_cnts[r*NN + src[idx]], 1);
        atomicAdd(&d_cntd[r*NN + dst[idx]], 1);
    }
}
__global__ void degs_k() {
    int i = blockIdx.x*blockDim.x + threadIdx.x;
    if (i < RR*NN) {
        int cs = d_cnts[i]; if (cs < 1) cs = 1;
        int cd = d_cntd[i]; if (cd < 1) cd = 1;
        d_rs[i] = rsqrtf((float)cs);
        d_rd[i] = rsqrtf((float)cd);
    }
}
// merged over relations via blockIdx.y
__global__ void scan_part_k() {
    __shared__ int sh[512];
    int r = blockIdx.y;
    const int* cnt = d_cntd + r*NN;
    int i = threadIdx.x;
    int d = blockIdx.x*512 + i;
    sh[i] = (d < NN) ? cnt[d] : 0;
    __syncthreads();
    for (int s = 256; s > 0; s >>= 1) { if (i < s) sh[i] += sh[i+s]; __syncthreads(); }
    if (i == 0) d_part[r*256 + blockIdx.x] = sh[0];
}
__global__ void scan_top_k(int nblk) {
    int r = threadIdx.x;
    if (r < RR) {
        int* part = d_part + r*256;
        int run = 0;
        for (int i = 0; i < nblk; i++) { int v = part[i]; part[i] = run; run += v; }
        d_off[r*(NN+1) + NN] = run;
    }
}
__global__ void scan_fill_k() {
    __shared__ int sh[512];
    int r = blockIdx.y;
    const int* cnt = d_cntd + r*NN;
    int i = threadIdx.x;
    int d = blockIdx.x*512 + i;
    int v = (d < NN) ? cnt[d] : 0;
    sh[i] = v;
    __syncthreads();
    for (int s = 1; s < 512; s <<= 1) {
        int tv = (i >= s) ? sh[i-s] : 0;
        __syncthreads();
        sh[i] += tv;
        __syncthreads();
    }
    if (d < NN) d_off[r*(NN+1) + d] = d_part[r*256 + blockIdx.x] + sh[i] - v;
}
__global__ void fill_adj_k(const int* __restrict__ src, const int* __restrict__ dst) {
    int idx = blockIdx.x*blockDim.x + threadIdx.x;
    if (idx < RR*EE) {
        int r = idx / EE;
        int dd = dst[idx];
        int p = d_off[r*(NN+1) + dd] + atomicAdd(&d_cur[r*NN + dd], 1);
        d_adj[r*EE + p] = src[idx];
    }
}

// ---------------- aggregation: bf16 hi/lo planes into cat cols [r*256, r*256+256) ----------------
__global__ void spmm_all_k(const float4* __restrict__ h4) {
    int d = blockIdx.x;
    int r = blockIdx.y;
    int j = threadIdx.x;               // 64 threads -> 64 float4 columns
    const int* off = d_off + r*(NN+1);
    const int* adj = d_adj + r*EE;
    const float* rs = d_rs + r*NN;
    int beg = off[d], end = off[d+1];
    float ax=0.f, ay=0.f, az=0.f, aw=0.f;
    int e = beg;
    for (; e + 1 < end; e += 2) {
        int s0 = adj[e], s1 = adj[e+1];
        float w0 = rs[s0], w1 = rs[s1];
        float4 v0 = h4[(size_t)s0*(HH/4) + j];
        float4 v1 = h4[(size_t)s1*(HH/4) + j];
        ax += v0.x*w0 + v1.x*w1;
        ay += v0.y*w0 + v1.y*w1;
        az += v0.z*w0 + v1.z*w1;
        aw += v0.w*w0 + v1.w*w1;
    }
    if (e < end) {
        int s0 = adj[e];
        float w0 = rs[s0];
        float4 v0 = h4[(size_t)s0*(HH/4) + j];
        ax += v0.x*w0; ay += v0.y*w0; az += v0.z*w0; aw += v0.w*w0;
    }
    float wd = d_rd[r*NN + d];
    ax *= wd; ay *= wd; az *= wd; aw *= wd;
    uint32_t h01, l01, h23, l23;
    split2(ax, ay, h01, l01);
    split2(az, aw, h23, l23);
    size_t u2 = (size_t)d*(KCATP/4) + r*(HH/4) + j;
    ((uint2*)d_chi)[u2] = make_uint2(h01, h23);
    ((uint2*)d_clo)[u2] = make_uint2(l01, l23);
}

// ---------------- weight pack: W seg [Kseg rows][256] fp32 -> B^T planes [256][Kp] at col kofs ----------------
__global__ void pack_seg_k(const float* __restrict__ W, int Ksrc, int Kseg,
                           int Kp, int kofs, int base, float scale) {
    int idx = blockIdx.x*blockDim.x + threadIdx.x;
    if (idx >= HH*Kseg) return;
    int n = idx / Kseg, k = idx % Kseg;
    float v = (k < Ksrc) ? W[(size_t)k*HH + n] * scale : 0.f;
    __nv_bfloat16 hi = __float2bfloat16(v);
    __nv_bfloat16 lo = __float2bfloat16(v - __bfloat162float(hi));
    size_t o = (size_t)base + (size_t)n*Kp + kofs + k;
    ((__nv_bfloat16*)d_bthi)[o] = hi;
    ((__nv_bfloat16*)d_btlo)[o] = lo;
}

// head pack: W_c2 [256][23] -> Bt planes [32][256] (rows >= 23 zero)
__global__ void pack_head_k(const float* __restrict__ W) {
    int idx = blockIdx.x*blockDim.x + threadIdx.x;
    if (idx >= 32*HH) return;
    int n = idx / HH, k = idx % HH;
    float v = (n < CC) ? W[(size_t)k*CC + n] : 0.f;
    __nv_bfloat16 hi = __float2bfloat16(v);
    __nv_bfloat16 lo = __float2bfloat16(v - __bfloat162float(hi));
    ((__nv_bfloat16*)d_bthi)[BT_C2 + idx] = hi;
    ((__nv_bfloat16*)d_btlo)[BT_C2 + idx] = lo;
}

// combined layer bias: mean(gcn_b) + skip_b
__global__ void comb_bias_k(const float* __restrict__ gcn_b, const float* __restrict__ skip_b) {
    int i = threadIdx.x + blockIdx.x*blockDim.x;
    if (i < LL*HH) {
        int l = i / HH, c = i % HH;
        const float* gb = gcn_b + (size_t)l*RR*HH;
        d_biasL[i] = (gb[c] + gb[HH+c] + gb[2*HH+c]) * (1.f/3.f) + skip_b[(size_t)l*HH + c];
    }
}

// ---------------- x convert: [N][300] fp32 -> planes [N][320] ----------------
__global__ void conv_x_k(const float* __restrict__ x) {
    int idx = blockIdx.x*blockDim.x + threadIdx.x;
    if (idx >= NN*XKP) return;
    int r = idx / XKP, k = idx % XKP;
    float v = (k < FF) ? x[(size_t)r*FF + k] : 0.f;
    __nv_bfloat16 hi = __float2bfloat16(v);
    __nv_bfloat16 lo = __float2bfloat16(v - __bfloat162float(hi));
    ((__nv_bfloat16*)d_xhi)[idx] = hi;
    ((__nv_bfloat16*)d_xlo)[idx] = lo;
}

// ---------------- tensor-core GEMM: C[M,256] = A[M,K] @ B^T (+bias) + fused BN stats ----------------
// CTA tile 64x256, 8 warps (2M x 4N), warp tile 32x64, k-chunk 32, 2-stage cp.async.
// Stage (40960B): A_hi[0,4K) A_lo[4K,8K) B_hi[8K,24K) B_lo[24K,40K)
// HARD CONSTRAINT: must stay <=128 regs for 2 CTAs/SM (65536-reg RF boundary).
#define STG 40960
#define GSMEM (2*STG)

__device__ __forceinline__ void g_load_stage(char* smemc, uint32_t sb, int st, int tid,
        int m0, int kc, int lda, int Kp,
        const __nv_bfloat16* Ahi, const __nv_bfloat16* Alo,
        const __nv_bfloat16* Bhi, const __nv_bfloat16* Blo)
{
    uint32_t base = sb + st*STG;
    char* cbase = smemc + st*STG;
    {
        int c = tid;                   // 256 A-chunks of 16B per plane
        int row = c >> 2, kp = c & 3;
        int gr = m0 + row;
        uint32_t off = row*64 + ((kp*16) ^ (((row>>1)&3)<<4));
        if (gr < NN) {
            size_t g = (size_t)gr*lda + kc*32 + kp*8;
            cpa16(base + off, Ahi + g);
            cpa16(base + 4096 + off, Alo + g);
        } else {
            *(uint4*)(cbase + off) = make_uint4(0,0,0,0);
            *(uint4*)(cbase + 4096 + off) = make_uint4(0,0,0,0);
        }
    }
    #pragma unroll
    for (int i = 0; i < 4; i++) {      // 1024 B-chunks per plane
        int c = tid + i*256;
        int n = c >> 2, kp = c & 3;
        uint32_t off = 8192 + n*64 + ((kp*16) ^ (((n>>1)&3)<<4));
        size_t g = (size_t)n*Kp + kc*32 + kp*8;
        cpa16(base + off, Bhi + g);
        cpa16(base + 16384 + off, Blo + g);
    }
    asm volatile("cp.async.commit_group;" ::: "memory");
}

// R14-verified compute stage (ldsm2 for B; 128 regs total)
__device__ __forceinline__ void g_compute_stage(uint32_t sb, int st, int lane, int wm, int wn,
        float acc[2][8][4])
{
    uint32_t aS = sb + st*STG;
    uint32_t bS = aS + 8192;
    #pragma unroll
    for (int k16 = 0; k16 < 2; k16++) {
        uint32_t ah[2][4], al[2][4];
        int arow = lane & 15;
        int akb = k16*32 + ((lane >> 4) << 4);
        #pragma unroll
        for (int t = 0; t < 2; t++) {
            int r = wm*32 + t*16 + arow;
            uint32_t ad = aS + r*64 + (akb ^ (((r>>1)&3)<<4));
            ldsm4(ah[t], ad);
            ldsm4(al[t], ad + 4096);
        }
        uint32_t bh[8][2], bl[8][2];
        int bn = lane & 7;
        int bkb = k16*32 + (((lane>>3)&1) << 4);
        #pragma unroll
        for (int u = 0; u < 8; u++) {
            int n = wn*64 + u*8 + bn;
            uint32_t bd = bS + n*64 + (bkb ^ (((n>>1)&3)<<4));
            ldsm2(bh[u], bd);
            ldsm2(bl[u], bd + 16384);
        }
        #pragma unroll
        for (int t = 0; t < 2; t++)
            #pragma unroll
            for (int u = 0; u < 8; u++) {
                mma16816(acc[t][u], ah[t], bh[u]);
                mma16816(acc[t][u], ah[t], bl[u]);
                mma16816(acc[t][u], al[t], bh[u]);
            }
    }
}

__global__ void __launch_bounds__(256, 2) gemm_mma_k(
        const __nv_bfloat16* __restrict__ Ahi, const __nv_bfloat16* __restrict__ Alo,
        int lda, int Kp,
        const __nv_bfloat16* __restrict__ Bhi, const __nv_bfloat16* __restrict__ Blo,
        const float* __restrict__ bias, float* __restrict__ C)
{
    extern __shared__ char smemc[];
    uint32_t sb = smem_u32(smemc);
    int tid = threadIdx.x, lane = tid & 31, wid = tid >> 5;
    int m0 = blockIdx.x * 64;
    int wm = wid & 1, wn = wid >> 1;

    float acc[2][8][4];
    #pragma unroll
    for (int t = 0; t < 2; t++)
        #pragma unroll
        for (int u = 0; u < 8; u++)
            #pragma unroll
            for (int q = 0; q < 4; q++) acc[t][u][q] = 0.f;

    int nch = Kp >> 5;
    // verified double-buffer: issue-next FIRST, then wait_group 1, sync, compute, sync
    g_load_stage(smemc, sb, 0, tid, m0, 0, lda, Kp, Ahi, Alo, Bhi, Blo);
    for (int kc = 0; kc < nch; kc++) {
        int st = kc & 1;
        if (kc + 1 < nch) {
            g_load_stage(smemc, sb, st^1, tid, m0, kc+1, lda, Kp, Ahi, Alo, Bhi, Blo);
            asm volatile("cp.async.wait_group 1;" ::: "memory");
        } else {
            asm volatile("cp.async.wait_group 0;" ::: "memory");
        }
        __syncthreads();
        g_compute_stage(sb, st, lane, wm, wn, acc);
        __syncthreads();
    }

    // ---- epilogue: bias + store + fused BN stats (sum, sumsq per column) ----
    float s0[16], s1[16];
    #pragma unroll
    for (int i = 0; i < 16; i++) { s0[i] = 0.f; s1[i] = 0.f; }
    #pragma unroll
    for (int t = 0; t < 2; t++) {
        int r0 = m0 + wm*32 + t*16 + (lane >> 2);
        #pragma unroll
        for (int u = 0; u < 8; u++) {
            int c0 = wn*64 + u*8 + (lane & 3)*2;
            float b0 = bias ? bias[c0]   : 0.f;
            float b1 = bias ? bias[c0+1] : 0.f;
            float v0 = acc[t][u][0] + b0;
            float v1 = acc[t][u][1] + b1;
            float v2 = acc[t][u][2] + b0;
            float v3 = acc[t][u][3] + b1;
            if (r0 < NN) {
                float2 v; v.x = v0; v.y = v1;
                *(float2*)(C + (size_t)r0*HH + c0) = v;
                s0[u*2+0] += v0; s1[u*2+0] += v0*v0;
                s0[u*2+1] += v1; s1[u*2+1] += v1*v1;
            }
            if (r0 + 8 < NN) {
                float2 v; v.x = v2; v.y = v3;
                *(float2*)(C + (size_t)(r0+8)*HH + c0) = v;
                s0[u*2+0] += v2; s1[u*2+0] += v2*v2;
                s0[u*2+1] += v3; s1[u*2+1] += v3*v3;
            }
        }
    }
    #pragma unroll
    for (int m = 4; m < 32; m <<= 1) {
        #pragma unroll
        for (int i = 0; i < 16; i++) {
            s0[i] += __shfl_xor_sync(0xffffffffu, s0[i], m);
            s1[i] += __shfl_xor_sync(0xffffffffu, s1[i], m);
        }
    }
    if (lane < 4) {
        #pragma unroll
        for (int u = 0; u < 8; u++)
            #pragma unroll
            for (int j = 0; j < 2; j++) {
                int c = wn*64 + u*8 + lane*2 + j;
                atomicAdd(&d_stats[c],      s0[u*2+j]);
                atomicAdd(&d_stats[HH + c], s1[u*2+j]);
            }
    }
}

// ---------------- MMA head: out[N,23] = h[N,256] @ W_c2 + b (bf16x3, B resident in smem) ----------------
// CTA: 128 thr (4 warps), tile 64 rows x 32 cols. B planes [32][256] fully in smem.
// smem: B_hi[0,16K) B_lo[16K,32K) ; A stages at 32K: st*(8K): A_hi[4K] A_lo[4K]
__global__ void __launch_bounds__(128) gemm_head_k(
        const __nv_bfloat16* __restrict__ Ahi, const __nv_bfloat16* __restrict__ Alo,
        int lda,
        const __nv_bfloat16* __restrict__ Bhi, const __nv_bfloat16* __restrict__ Blo,
        const float* __restrict__ bias, float* __restrict__ C)
{
    __shared__ char smemc[49152];
    uint32_t sb = smem_u32(smemc);
    int tid = threadIdx.x, lane = tid & 31, wid = tid >> 5;
    int m0 = blockIdx.x * 64;

    // load full B (8 chunks x 32n x 64B per plane), group 0
    for (int i = tid; i < 1024; i += 128) {
        int c = i >> 7, rem = i & 127;
        int n = rem >> 2, kp = rem & 3;
        uint32_t off = c*2048 + n*64 + ((kp*16) ^ (((n>>1)&3)<<4));
        size_t g = (size_t)n*HH + c*32 + kp*8;
        cpa16(sb + off, Bhi + g);
        cpa16(sb + 16384 + off, Blo + g);
    }
    asm volatile("cp.async.commit_group;" ::: "memory");

    auto loadA = [&](int st, int kc) {
        uint32_t base = sb + 32768 + st*8192;
        #pragma unroll
        for (int i = 0; i < 2; i++) {
            int c = tid + i*128;
            int row = c >> 2, kp = c & 3;
            int gr = m0 + row;
            uint32_t off = row*64 + ((kp*16) ^ (((row>>1)&3)<<4));
            if (gr < NN) {
                size_t g = (size_t)gr*lda + kc*32 + kp*8;
                cpa16(base + off, Ahi + g);
                cpa16(base + 4096 + off, Alo + g);
            } else {
                *(uint4*)(smemc + 32768 + st*8192 + off) = make_uint4(0,0,0,0);
                *(uint4*)(smemc + 32768 + st*8192 + 4096 + off) = make_uint4(0,0,0,0);
            }
        }
        asm volatile("cp.async.commit_group;" ::: "memory");
    };

    float acc[4][4];
    #pragma unroll
    for (int u = 0; u < 4; u++)
        #pragma unroll
        for (int q = 0; q < 4; q++) acc[u][q] = 0.f;

    loadA(0, 0);
    for (int kc = 0; kc < 8; kc++) {
        int st = kc & 1;
        if (kc + 1 < 8) {
            loadA(st^1, kc+1);
            asm volatile("cp.async.wait_group 1;" ::: "memory");
        } else {
            asm volatile("cp.async.wait_group 0;" ::: "memory");
        }
        __syncthreads();
        uint32_t aS = sb + 32768 + st*8192;
        uint32_t bS = sb + kc*2048;
        #pragma unroll
        for (int k16 = 0; k16 < 2; k16++) {
            uint32_t ah[4], al[4];
            int r = wid*16 + (lane & 15);
            int akb = k16*32 + ((lane >> 4) << 4);
            uint32_t ad = aS + r*64 + (akb ^ (((r>>1)&3)<<4));
            ldsm4(ah, ad);
            ldsm4(al, ad + 4096);
            uint32_t bh[4][2], bl[4][2];
            int bn_ = lane & 7;
            int nofs = ((lane >> 4) & 1) * 8;
            int bkb = k16*32 + (((lane>>3)&1) << 4);
            #pragma unroll
            for (int u2 = 0; u2 < 2; u2++) {
                int n = u2*16 + nofs + bn_;
                uint32_t bd = bS + n*64 + (bkb ^ (((n>>1)&3)<<4));
                ldsm4(&bh[u2*2][0], bd);
                ldsm4(&bl[u2*2][0], bd + 16384);
            }
            #pragma unroll
            for (int u = 0; u < 4; u++) {
                mma16816(acc[u], ah, bh[u]);
                mma16816(acc[u], ah, bl[u]);
                mma16816(acc[u], al, bh[u]);
            }
        }
        __syncthreads();
    }

    int r0 = m0 + wid*16 + (lane >> 2);
    #pragma unroll
    for (int u = 0; u < 4; u++) {
        int c0 = u*8 + (lane & 3)*2;
        float b0 = (c0 < CC)   ? bias[c0]   : 0.f;
        float b1 = (c0+1 < CC) ? bias[c0+1] : 0.f;
        if (r0 < NN) {
            if (c0 < CC)   C[(size_t)r0*CC + c0]   = acc[u][0] + b0;
            if (c0+1 < CC) C[(size_t)r0*CC + c0+1] = acc[u][1] + b1;
        }
        if (r0 + 8 < NN) {
            if (c0 < CC)   C[(size_t)(r0+8)*CC + c0]   = acc[u][2] + b0;
            if (c0+1 < CC) C[(size_t)(r0+8)*CC + c0+1] = acc[u][3] + b1;
        }
    }
}

// ---------------- BatchNorm ----------------
__global__ void zero_stats_k() {
    int i = threadIdx.x;
    if (i < 2*HH) d_stats[i] = 0.f;
}
// finalize + re-zero stats for the next GEMM's atomics
__global__ void bn_fin_k(const float* __restrict__ g, const float* __restrict__ b) {
    int j = threadIdx.x;
    float mean = d_stats[j] * (1.f/NN);
    float var  = d_stats[HH+j] * (1.f/NN) - mean*mean;
    float a = g[j] * rsqrtf(var + 1e-5f);
    d_ab[j] = a;
    d_ab[HH+j] = b[j] - mean*a;
    d_stats[j] = 0.f;
    d_stats[HH+j] = 0.f;
}
// mode 0: relu, 1: leaky_relu(0.01); planes: also write bf16 hi/lo into cat cols 768..1023
__global__ void bn_apply_k(const float4* __restrict__ in, float4* __restrict__ outp,
                           int mode, int planes) {
    int i = blockIdx.x*blockDim.x + threadIdx.x;
    if (i < NH/4) {
        int j = (i*4) & (HH-1);
        float4 v = in[i];
        float r0 = d_ab[j+0]*v.x + d_ab[HH+j+0];
        float r1 = d_ab[j+1]*v.y + d_ab[HH+j+1];
        float r2 = d_ab[j+2]*v.z + d_ab[HH+j+2];
        float r3 = d_ab[j+3]*v.w + d_ab[HH+j+3];
        if (mode == 0) {
            r0 = fmaxf(r0, 0.f); r1 = fmaxf(r1, 0.f);
            r2 = fmaxf(r2, 0.f); r3 = fmaxf(r3, 0.f);
        } else {
            r0 = (r0 > 0.f) ? r0 : 0.01f*r0;
            r1 = (r1 > 0.f) ? r1 : 0.01f*r1;
            r2 = (r2 > 0.f) ? r2 : 0.01f*r2;
            r3 = (r3 > 0.f) ? r3 : 0.01f*r3;
        }
        float4 o; o.x = r0; o.y = r1; o.z = r2; o.w = r3;
        outp[i] = o;
        if (planes) {
            uint32_t h01, l01, h23, l23;
            split2(r0, r1, h01, l01);
            split2(r2, r3, h23, l23);
            int row = i >> 6;          // HH/4 = 64 float4 per row
            int cj  = i & 63;
            size_t u2 = (size_t)row*(KCATP/4) + (KCAT/4) + cj;
            ((uint2*)d_chi)[u2] = make_uint2(h01, h23);
            ((uint2*)d_clo)[u2] = make_uint2(l01, l23);
        }
    }
}

extern "C" void kernel_launch(void* const* d_in, const int* in_sizes, int n_in,
                              void* d_out, int out_size) {
    (void)in_sizes; (void)n_in; (void)out_size;
    const float* x         = (const float*)d_in[0];
    const int*   esrc      = (const int*)  d_in[1];
    const int*   edst      = (const int*)  d_in[2];
    const float* W_feat    = (const float*)d_in[3];
    const float* b_feat    = (const float*)d_in[4];
    const float* g_feat    = (const float*)d_in[5];
    const float* beta_feat = (const float*)d_in[6];
    const float* gcn_W     = (const float*)d_in[7];
    const float* gcn_b     = (const float*)d_in[8];
    const float* skip_W    = (const float*)d_in[9];
    const float* skip_b    = (const float*)d_in[10];
    const float* bn_g      = (const float*)d_in[11];
    const float* bn_b      = (const float*)d_in[12];
    const float* W_c1      = (const float*)d_in[13];
    const float* b_c1      = (const float*)d_in[14];
    const float* g_c       = (const float*)d_in[15];
    const float* beta_c    = (const float*)d_in[16];
    const float* W_c2      = (const float*)d_in[17];
    const float* b_c2      = (const float*)d_in[18];
    float* out = (float*)d_out;

    float *h, *t, *biasL;
    void *xhi, *xlo, *chi, *clo, *bthi, *btlo;
    cudaGetSymbolAddress((void**)&h,     d_h);
    cudaGetSymbolAddress((void**)&t,     d_t);
    cudaGetSymbolAddress((void**)&biasL, d_biasL);
    cudaGetSymbolAddress(&xhi, d_xhi);   cudaGetSymbolAddress(&xlo, d_xlo);
    cudaGetSymbolAddress(&chi, d_chi);   cudaGetSymbolAddress(&clo, d_clo);
    cudaGetSymbolAddress(&bthi, d_bthi); cudaGetSymbolAddress(&btlo, d_btlo);
    const __nv_bfloat16* XHI = (const __nv_bfloat16*)xhi;
    const __nv_bfloat16* XLO = (const __nv_bfloat16*)xlo;
    const __nv_bfloat16* CHI = (const __nv_bfloat16*)chi;
    const __nv_bfloat16* CLO = (const __nv_bfloat16*)clo;
    const __nv_bfloat16* BHI = (const __nv_bfloat16*)bthi;
    const __nv_bfloat16* BLO = (const __nv_bfloat16*)btlo;

    cudaFuncSetAttribute(gemm_mma_k, cudaFuncAttributeMaxDynamicSharedMemorySize, GSMEM);

    const int NBLK = (NN + 511) / 512;
    const int GG = (NN + 63)/64;

    // ---- launches 1..3, then gemm as my 4th launch (ncu: harness offset 2, -s 5 -> my #4) ----
    conv_x_k<<<(NN*XKP + 255)/256, 256>>>(x);                                   // 1
    pack_seg_k<<<(HH*XKP + 255)/256, 256>>>(W_feat, FF, XKP, XKP, 0, BT_FEAT, 1.f);  // 2
    zero_stats_k<<<1, 512>>>();                                                 // 3
    gemm_mma_k<<<GG, 256, GSMEM>>>(XHI, XLO, XKP, XKP, BHI + BT_FEAT, BLO + BT_FEAT,
                                   b_feat, t);                                  // 4  <- profiled
    bn_fin_k<<<1, 256>>>(g_feat, beta_feat);
    bn_apply_k<<<(NH/4 + 255)/256, 256>>>((const float4*)t, (float4*)h, 0, 1);

    // ---- remaining weight packs + combined biases ----
    pack_seg_k<<<(HH*KCAT + 255)/256, 256>>>(gcn_W,             KCAT, KCAT, KCATP, 0, BT_L0, 1.f/3.f);
    pack_seg_k<<<(HH*HH   + 255)/256, 256>>>(skip_W,            HH, HH, KCATP, KCAT, BT_L0, 1.f);
    pack_seg_k<<<(HH*KCAT + 255)/256, 256>>>(gcn_W + RR*HH*HH,  KCAT, KCAT, KCATP, 0, BT_L1, 1.f/3.f);
    pack_seg_k<<<(HH*HH   + 255)/256, 256>>>(skip_W + HH*HH,    HH, HH, KCATP, KCAT, BT_L1, 1.f);
    pack_seg_k<<<(HH*HH   + 255)/256, 256>>>(W_c1,              HH, HH, HH, 0, BT_C1, 1.f);
    pack_head_k<<<(32*HH + 255)/256, 256>>>(W_c2);
    comb_bias_k<<<2, 256>>>(gcn_b, skip_b);

    // ---- graph build (relations merged via grid.y) ----
    zero_graph_k<<<(RR*NN + 255)/256, 256>>>();
    count_k<<<(RR*EE + 255)/256, 256>>>(esrc, edst);
    degs_k<<<(RR*NN + 255)/256, 256>>>();
    dim3 sp(NBLK, RR);
    scan_part_k<<<sp, 512>>>();
    scan_top_k<<<1, 32>>>(NBLK);
    scan_fill_k<<<sp, 512>>>();
    fill_adj_k<<<(RR*EE + 255)/256, 256>>>(esrc, edst);

    // ---- GCN layers: single fused GEMM per layer (A=[m0|m1|m2|h], K=1024) ----
    for (int l = 0; l < LL; l++) {
        int btl = l ? BT_L1 : BT_L0;
        dim3 sg(NN, RR);
        spmm_all_k<<<sg, 64>>>((const float4*)h);
        gemm_mma_k<<<GG, 256, GSMEM>>>(CHI, CLO, KCATP, KCATP, BHI + btl, BLO + btl,
                                       biasL + l*HH, t);
        bn_fin_k<<<1, 256>>>(bn_g + l*HH, bn_b + l*HH);
        bn_apply_k<<<(NH/4 + 255)/256, 256>>>((const float4*)t, (float4*)h, 1, 1);
    }

    // ---- classification head (A = h planes inside cat buffer, lda=1024) ----
    gemm_mma_k<<<GG, 256, GSMEM>>>(CHI + KCAT, CLO + KCAT, KCATP, HH,
                                   BHI + BT_C1, BLO + BT_C1, b_c1, t);
    bn_fin_k<<<1, 256>>>(g_c, beta_c);
    bn_apply_k<<<(NH/4 + 255)/256, 256>>>((const float4*)t, (float4*)h, 0, 1);
    gemm_head_k<<<GG, 128>>>(CHI + KCAT, CLO + KCAT, KCATP,
                             BHI + BT_C2, BLO + BT_C2, b_c2, out);
}